// round 5
// baseline (speedup 1.0000x reference)
#include <cuda_runtime.h>

// R-MAC over x[32, 2048, 32, 32] -> out[32, 2048].
// 19 static regions (H=W=32): 1x full (32x32), 6x 21x21 (rows {0,5,11} x cols
// {0,11}), 12x 16x16 (rows {0,5,10,16} x cols {0,8,16}).
// Column segments: s1=[0,21) s2=[11,32) s3=[0,16) s4=[8,24) s5=[16,32).
// Region row-ranges decompose into boundary-aligned row blocks:
//   segs 1,2 (fam B): blocks [0,5)[5,11)[11,16)[16,21)[21,26)[26,32)
//   segs 3,4,5 (fam C): blocks [0,5)[5,10)[10,16)[16,21)[21,26)[26,32)
// Full image = max over bmbuf entries of segs 1,2 (cols [0,21)u[11,32)=[0,32),
// rows: all blocks).

#define WPB 8
#define TPW 4
#define NTILES (32 * 2048)

__constant__ int c_start[2][6] = {{0, 5, 11, 16, 21, 26}, {0, 5, 10, 16, 21, 26}};
__constant__ int c_sz6[2][6]   = {{0, 1, 0, 0, 0, 1},     {0, 0, 1, 0, 0, 1}};
// region 1..18 -> base index into bmbuf ((seg-1)*6 + first block), +1 if 4 blocks
__constant__ int c_rbase[19] = {0, 0, 6, 1, 7, 2, 8,
                                12, 18, 24, 13, 19, 25, 14, 20, 26, 15, 21, 27};
__constant__ int c_rcnt4[19] = {0, 1, 1, 1, 1, 1, 1, 0, 0, 0, 0, 0, 0, 0, 0, 0, 0, 0, 0};

__global__ __launch_bounds__(32 * WPB, 2)
void rmac_kernel(const float* __restrict__ x, float* __restrict__ out) {
    // Per-warp scratch (warp-private; ordered by __syncwarp).
    __shared__ float gbuf[WPB][32 * 9];   // 32 rows x 8 col-group maxes, stride 9
    __shared__ float rbuf[WPB][64];       // col-11 and col-20 per row
    __shared__ float segm[WPB][32 * 7];   // per-row segment maxes, stride 7
    __shared__ float bmbuf[WPB][32];      // 30 (seg,block) maxes
    __shared__ float rsum[WPB][20];       // region maxes for the final sum

    const int wib  = threadIdx.x >> 5;
    const int lane = threadIdx.x & 31;
    const int wg   = blockIdx.x * WPB + wib;        // global warp id
    const size_t tbase = (size_t)wg * TPW;          // first tile of this warp
    const int a  = lane >> 3;                       // row sub-index per k-step
    const int cg = lane & 7;                        // column group (4 cols)

    const float4* __restrict__ src =
        reinterpret_cast<const float4*>(x + tbase * 1024);

    // Prologue: issue tile 0's loads.
    float4 v[8];
#pragma unroll
    for (int k = 0; k < 8; k++) v[k] = __ldcs(src + k * 32 + lane);

    float* g = gbuf[wib];

#pragma unroll
    for (int it = 0; it < TPW; it++) {
        // ---- Stage 1: reduce arriving tile into smem (v dies here) ----
#pragma unroll
        for (int k = 0; k < 8; k++) {
            const int row = 4 * k + a;
            float m = fmaxf(fmaxf(v[k].x, v[k].y), fmaxf(v[k].z, v[k].w));
            g[row * 9 + cg] = m;
            if (cg == 2) rbuf[wib][row] = v[k].w;       // col 11
            if (cg == 5) rbuf[wib][32 + row] = v[k].x;  // col 20
        }
        __syncwarp();

        // ---- Prefetch next tile into the (now dead) v registers ----
        if (it + 1 < TPW) {
            const float4* __restrict__ ns = src + (size_t)(it + 1) * 256;
#pragma unroll
            for (int k = 0; k < 8; k++) v[k] = __ldcs(ns + k * 32 + lane);
        }

        // ---- Stage 2: lane = row; 6 column-segment maxes ----
        float gg[8];
#pragma unroll
        for (int c = 0; c < 8; c++) gg[c] = g[lane * 9 + c];
        const float r11 = rbuf[wib][lane];
        const float r20 = rbuf[wib][32 + lane];

        const float s3 = fmaxf(fmaxf(gg[0], gg[1]), fmaxf(gg[2], gg[3]));  // [0,16)
        const float s4 = fmaxf(fmaxf(gg[2], gg[3]), fmaxf(gg[4], gg[5]));  // [8,24)
        const float s5 = fmaxf(fmaxf(gg[4], gg[5]), fmaxf(gg[6], gg[7]));  // [16,32)
        const float s1 = fmaxf(s3, fmaxf(gg[4], r20));                     // [0,21)
        const float s2 = fmaxf(r11, fmaxf(gg[3], s5));                     // [11,32)

        float* sd = segm[wib] + lane * 7;
        sd[1] = s1; sd[2] = s2; sd[3] = s3; sd[4] = s4; sd[5] = s5;
        __syncwarp();

        // ---- Stage 3a: 30 (segment, row-block) maxes ----
        if (lane < 30) {
            const int s   = 1 + lane / 6;
            const int blk = lane % 6;
            const int fam = (s >= 3);
            const int st  = c_start[fam][blk];
            const float* sp = segm[wib] + s;
            float bm = sp[st * 7];
#pragma unroll
            for (int q = 1; q < 5; q++) bm = fmaxf(bm, sp[(st + q) * 7]);
            if (c_sz6[fam][blk]) bm = fmaxf(bm, sp[(st + 5) * 7]);
            bmbuf[wib][lane] = bm;
        }
        __syncwarp();

        // ---- Stage 3b: region maxes into rsum (lane 0 pads, lane 19 zeros) ----
        if (lane >= 1 && lane < 19) {
            const float* bp = bmbuf[wib];
            const int base = c_rbase[lane];
            float m = fmaxf(fmaxf(bp[base], bp[base + 1]), bp[base + 2]);
            if (c_rcnt4[lane]) m = fmaxf(m, bp[base + 3]);
            rsum[wib][lane] = m;
        } else if (lane == 19) {
            rsum[wib][19] = 0.0f;
        } else if (lane == 0) {
            rsum[wib][0] = 0.0f;
        }
        __syncwarp();

        // ---- Final: lane 0 computes full-image max + sum of 19 regions ----
        if (lane == 0) {
            const float4 b0 = *reinterpret_cast<const float4*>(&bmbuf[wib][0]);
            const float4 b1 = *reinterpret_cast<const float4*>(&bmbuf[wib][4]);
            const float4 b2 = *reinterpret_cast<const float4*>(&bmbuf[wib][8]);
            float full = fmaxf(fmaxf(fmaxf(b0.x, b0.y), fmaxf(b0.z, b0.w)),
                               fmaxf(fmaxf(b1.x, b1.y), fmaxf(b1.z, b1.w)));
            full = fmaxf(full, fmaxf(fmaxf(b2.x, b2.y), fmaxf(b2.z, b2.w)));

            const float4 q0 = *reinterpret_cast<const float4*>(&rsum[wib][0]);
            const float4 q1 = *reinterpret_cast<const float4*>(&rsum[wib][4]);
            const float4 q2 = *reinterpret_cast<const float4*>(&rsum[wib][8]);
            const float4 q3 = *reinterpret_cast<const float4*>(&rsum[wib][12]);
            const float4 q4 = *reinterpret_cast<const float4*>(&rsum[wib][16]);
            float acc = ((q0.x + q0.y) + (q0.z + q0.w))
                      + ((q1.x + q1.y) + (q1.z + q1.w))
                      + ((q2.x + q2.y) + (q2.z + q2.w))
                      + ((q3.x + q3.y) + (q3.z + q3.w))
                      + ((q4.x + q4.y) + (q4.z + q4.w))
                      + full;
            out[tbase + it] = acc;
        }
        __syncwarp();
    }
}

extern "C" void kernel_launch(void* const* d_in, const int* in_sizes, int n_in,
                              void* d_out, int out_size) {
    const float* x = (const float*)d_in[0];
    float* out = (float*)d_out;
    (void)in_sizes; (void)n_in; (void)out_size;
    rmac_kernel<<<NTILES / (WPB * TPW), 32 * WPB>>>(x, out);
}

// round 7
// speedup vs baseline: 1.0058x; 1.0058x over previous
#include <cuda_runtime.h>

// R-MAC over x[32, 2048, 32, 32] -> out[32, 2048].
// 19 static regions (H=W=32): 1x full (32x32), 6x 21x21 (rows {0,5,11} x cols
// {0,11}), 12x 16x16 (rows {0,5,10,16} x cols {0,8,16}).
// Column segments: s1=[0,21) s2=[11,32) s3=[0,16) s4=[8,24) s5=[16,32).
// Region row-ranges decompose into boundary-aligned row blocks:
//   segs 1,2 (fam B): blocks [0,5)[5,11)[11,16)[16,21)[21,26)[26,32)
//   segs 3,4,5 (fam C): blocks [0,5)[5,10)[10,16)[16,21)[21,26)[26,32)
// Full image = max over bmbuf of segs 1,2 (cols [0,21)u[11,32)=[0,32), all rows).

#define WPB 8
#define TPW 4
#define NTILES (32 * 2048)

__constant__ int c_start[2][6] = {{0, 5, 11, 16, 21, 26}, {0, 5, 10, 16, 21, 26}};
__constant__ int c_sz6[2][6]   = {{0, 1, 0, 0, 0, 1},     {0, 0, 1, 0, 0, 1}};
// region 1..18 -> base index into bmbuf ((seg-1)*6 + first block), +1 if 4 blocks
__constant__ int c_rbase[19] = {0, 0, 6, 1, 7, 2, 8,
                                12, 18, 24, 13, 19, 25, 14, 20, 26, 15, 21, 27};
__constant__ int c_rcnt4[19] = {0, 1, 1, 1, 1, 1, 1, 0, 0, 0, 0, 0, 0, 0, 0, 0, 0, 0, 0};

// minBlocksPerMultiprocessor=4 caps regs at 64 -> 4 blocks/SM = 32 resident
// warps, each holding ~1KB of loads in flight nearly full-time.
__global__ __launch_bounds__(32 * WPB, 4)
void rmac_kernel(const float* __restrict__ x, float* __restrict__ out) {
    // Per-warp scratch (warp-private; ordered by __syncwarp).
    __shared__ float gbuf[WPB][32 * 9];   // 32 rows x 8 col-group maxes, stride 9
    __shared__ float rbuf[WPB][64];       // col-11 and col-20 per row
    __shared__ float segm[WPB][32 * 7];   // per-row segment maxes, stride 7
    __shared__ float bmbuf[WPB][32];      // 30 (seg,block) maxes
    __shared__ float rsum[WPB][20];       // region maxes for the final sum

    const int wib  = threadIdx.x >> 5;
    const int lane = threadIdx.x & 31;
    const int wg   = blockIdx.x * WPB + wib;        // global warp id
    const size_t tbase = (size_t)wg * TPW;          // first tile of this warp
    const int a  = lane >> 3;                       // row sub-index per k-step
    const int cg = lane & 7;                        // column group (4 cols)

    const float4* __restrict__ src =
        reinterpret_cast<const float4*>(x + tbase * 1024);

    // Prologue: issue tile 0's loads.
    float4 v[8];
#pragma unroll
    for (int k = 0; k < 8; k++) v[k] = __ldcs(src + k * 32 + lane);

    float* g = gbuf[wib];

#pragma unroll
    for (int it = 0; it < TPW; it++) {
        // ---- Stage 1: reduce arriving tile into smem (v dies here) ----
#pragma unroll
        for (int k = 0; k < 8; k++) {
            const int row = 4 * k + a;
            float m = fmaxf(fmaxf(v[k].x, v[k].y), fmaxf(v[k].z, v[k].w));
            g[row * 9 + cg] = m;
            if (cg == 2) rbuf[wib][row] = v[k].w;       // col 11
            if (cg == 5) rbuf[wib][32 + row] = v[k].x;  // col 20
        }
        __syncwarp();

        // ---- Prefetch next tile into the (now dead) v registers ----
        if (it + 1 < TPW) {
            const float4* __restrict__ ns = src + (size_t)(it + 1) * 256;
#pragma unroll
            for (int k = 0; k < 8; k++) v[k] = __ldcs(ns + k * 32 + lane);
        }

        // ---- Stage 2: lane = row; build column-segment maxes ----
        float gg[8];
#pragma unroll
        for (int c = 0; c < 8; c++) gg[c] = g[lane * 9 + c];
        const float r11 = rbuf[wib][lane];
        const float r20 = rbuf[wib][32 + lane];

        const float s3 = fmaxf(fmaxf(gg[0], gg[1]), fmaxf(gg[2], gg[3]));  // [0,16)
        const float s4 = fmaxf(fmaxf(gg[2], gg[3]), fmaxf(gg[4], gg[5]));  // [8,24)
        const float s5 = fmaxf(fmaxf(gg[4], gg[5]), fmaxf(gg[6], gg[7]));  // [16,32)
        const float s1 = fmaxf(s3, fmaxf(gg[4], r20));                     // [0,21)
        const float s2 = fmaxf(r11, fmaxf(gg[3], s5));                     // [11,32)

        float* sd = segm[wib] + lane * 7;
        sd[1] = s1; sd[2] = s2; sd[3] = s3; sd[4] = s4; sd[5] = s5;
        __syncwarp();

        // ---- Stage 3a: 30 (segment, row-block) maxes ----
        if (lane < 30) {
            const int s   = 1 + lane / 6;
            const int blk = lane % 6;
            const int fam = (s >= 3);
            const int st  = c_start[fam][blk];
            const float* sp = segm[wib] + s;
            float bm = sp[st * 7];
#pragma unroll
            for (int q = 1; q < 5; q++) bm = fmaxf(bm, sp[(st + q) * 7]);
            if (c_sz6[fam][blk]) bm = fmaxf(bm, sp[(st + 5) * 7]);
            bmbuf[wib][lane] = bm;
        }
        __syncwarp();

        // ---- Stage 3b: region maxes into rsum (lanes 0/19 zero-pad) ----
        if (lane >= 1 && lane < 19) {
            const float* bp = bmbuf[wib];
            const int base = c_rbase[lane];
            float m = fmaxf(fmaxf(bp[base], bp[base + 1]), bp[base + 2]);
            if (c_rcnt4[lane]) m = fmaxf(m, bp[base + 3]);
            rsum[wib][lane] = m;
        } else if (lane == 19) {
            rsum[wib][19] = 0.0f;
        } else if (lane == 0) {
            rsum[wib][0] = 0.0f;
        }
        __syncwarp();

        // ---- Final: lane 0 computes full-image max + sum of 19 regions ----
        if (lane == 0) {
            const float4 b0 = *reinterpret_cast<const float4*>(&bmbuf[wib][0]);
            const float4 b1 = *reinterpret_cast<const float4*>(&bmbuf[wib][4]);
            const float4 b2 = *reinterpret_cast<const float4*>(&bmbuf[wib][8]);
            float full = fmaxf(fmaxf(fmaxf(b0.x, b0.y), fmaxf(b0.z, b0.w)),
                               fmaxf(fmaxf(b1.x, b1.y), fmaxf(b1.z, b1.w)));
            full = fmaxf(full, fmaxf(fmaxf(b2.x, b2.y), fmaxf(b2.z, b2.w)));

            const float4 q0 = *reinterpret_cast<const float4*>(&rsum[wib][0]);
            const float4 q1 = *reinterpret_cast<const float4*>(&rsum[wib][4]);
            const float4 q2 = *reinterpret_cast<const float4*>(&rsum[wib][8]);
            const float4 q3 = *reinterpret_cast<const float4*>(&rsum[wib][12]);
            const float4 q4 = *reinterpret_cast<const float4*>(&rsum[wib][16]);
            float acc = ((q0.x + q0.y) + (q0.z + q0.w))
                      + ((q1.x + q1.y) + (q1.z + q1.w))
                      + ((q2.x + q2.y) + (q2.z + q2.w))
                      + ((q3.x + q3.y) + (q3.z + q3.w))
                      + ((q4.x + q4.y) + (q4.z + q4.w))
                      + full;
            out[tbase + it] = acc;
        }
        __syncwarp();
    }
}

extern "C" void kernel_launch(void* const* d_in, const int* in_sizes, int n_in,
                              void* d_out, int out_size) {
    const float* x = (const float*)d_in[0];
    float* out = (float*)d_out;
    (void)in_sizes; (void)n_in; (void)out_size;
    rmac_kernel<<<NTILES / (WPB * TPW), 32 * WPB>>>(x, out);
}

// round 9
// speedup vs baseline: 1.1339x; 1.1274x over previous
#include <cuda_runtime.h>
#include <cstdint>

// R-MAC over x[32, 2048, 32, 32] -> out[32, 2048].
// 19 static regions (H=W=32): 1x full (32x32), 6x 21x21 (rows {0,5,11} x cols
// {0,11}), 12x 16x16 (rows {0,5,10,16} x cols {0,8,16}).
// Column segments: s1=[0,21) s2=[11,32) s3=[0,16) s4=[8,24) s5=[16,32).
// Row-block decomposition:
//   segs 1,2 (fam B): blocks [0,5)[5,11)[11,16)[16,21)[21,26)[26,32)
//   segs 3,4,5 (fam C): blocks [0,5)[5,10)[10,16)[16,21)[21,26)[26,32)
// Full image = max over bmbuf of segs 1,2 (cols [0,21)u[11,32)=[0,32), all rows).

#define WPB   8
#define DEPTH 3
#define TPW   4
#define NTILES (32 * 2048)
#define DYN_SMEM (WPB * DEPTH * 4096)

__constant__ int c_start[2][6] = {{0, 5, 11, 16, 21, 26}, {0, 5, 10, 16, 21, 26}};
__constant__ int c_sz6[2][6]   = {{0, 1, 0, 0, 0, 1},     {0, 0, 1, 0, 0, 1}};
__constant__ int c_rbase[19] = {0, 0, 6, 1, 7, 2, 8,
                                12, 18, 24, 13, 19, 25, 14, 20, 26, 15, 21, 27};
__constant__ int c_rcnt4[19] = {0, 1, 1, 1, 1, 1, 1, 0, 0, 0, 0, 0, 0, 0, 0, 0, 0, 0, 0};

__device__ __forceinline__ void cpa16(uint32_t dst_smem, const void* src) {
    asm volatile("cp.async.cg.shared.global [%0], [%1], 16;"
                 :: "r"(dst_smem), "l"(src) : "memory");
}
__device__ __forceinline__ void cpa_commit() {
    asm volatile("cp.async.commit_group;" ::: "memory");
}
template <int N>
__device__ __forceinline__ void cpa_wait() {
    asm volatile("cp.async.wait_group %0;" :: "n"(N) : "memory");
}
// Per-thread groups committed before the wait at iter `it` is
// min(TPW, DEPTH + it); group #it must be complete, so wait until
// <= committed - (it+1) groups pending. Constant-folds under full unroll.
__device__ __forceinline__ void cpa_wait_iter(int it) {
    const int committed = (DEPTH + it < TPW) ? (DEPTH + it) : TPW;
    const int n = committed - (it + 1);
    switch (n) {
        case 0: cpa_wait<0>(); break;
        case 1: cpa_wait<1>(); break;
        case 2: cpa_wait<2>(); break;
        default: cpa_wait<0>(); break;
    }
}

__global__ __launch_bounds__(32 * WPB)
void rmac_kernel(const float* __restrict__ x, float* __restrict__ out) {
    extern __shared__ float4 ring[];      // [WPB][DEPTH][256] float4 = 96 KB
    __shared__ float segm[WPB][32 * 7];   // per-row segment maxes, stride 7
    __shared__ float bmbuf[WPB][32];      // 30 (seg,block) maxes
    __shared__ float rsum[WPB][20];       // region maxes for the final sum

    const int wib  = threadIdx.x >> 5;
    const int lane = threadIdx.x & 31;
    const int wg   = blockIdx.x * WPB + wib;
    const size_t tbase = (size_t)wg * TPW;

    const float4* __restrict__ x4 = reinterpret_cast<const float4*>(x);
    const uint32_t ring0 =
        (uint32_t)__cvta_generic_to_shared(ring) + (uint32_t)(wib * DEPTH * 4096);

    // Write mapping: lane l, op k holds tile quad (k*32+l) = row 4k+(l>>3),
    // 16B-group c=l&7. Store XOR-swizzled: group slot c ^ (row&7).
    const int wrow_a = lane >> 3;
    const int wc     = lane & 7;

    auto issue_tile = [&](int slot, int it) {
        const float4* src = x4 + (tbase + it) * 256;
        const uint32_t sb = ring0 + (uint32_t)slot * 4096;
#pragma unroll
        for (int k = 0; k < 8; k++) {
            const int row = 4 * k + wrow_a;
            const uint32_t dst = sb + (uint32_t)((row * 8 + (wc ^ (row & 7))) * 16);
            cpa16(dst, src + k * 32 + lane);
        }
        cpa_commit();
    };

    // Prologue: fill the ring (groups 0..DEPTH-1 = tiles 0..DEPTH-1).
#pragma unroll
    for (int d = 0; d < DEPTH; d++) issue_tile(d, d);

    const int r  = lane;                  // this lane reduces row r
    const int rx = r & 7;

#pragma unroll
    for (int it = 0; it < TPW; it++) {
        const int slot = it % DEPTH;
        cpa_wait_iter(it);                // guarantee group #it (this slot) done
        __syncwarp();                     // publish all lanes' copies

        // ---- Row reduce straight from swizzled smem (lane = row) ----
        const float4* B = ring + (size_t)(wib * DEPTH + slot) * 256 + r * 8;
        float4 q[8];
#pragma unroll
        for (int g = 0; g < 8; g++) q[g] = B[g ^ rx];   // conflict-free LDS.128
        float m[8];
#pragma unroll
        for (int g = 0; g < 8; g++)
            m[g] = fmaxf(fmaxf(q[g].x, q[g].y), fmaxf(q[g].z, q[g].w));
        const float r11 = q[2].w;         // col 11
        const float r20 = q[5].x;         // col 20

        const float s3 = fmaxf(fmaxf(m[0], m[1]), fmaxf(m[2], m[3]));  // [0,16)
        const float s4 = fmaxf(fmaxf(m[2], m[3]), fmaxf(m[4], m[5]));  // [8,24)
        const float s5 = fmaxf(fmaxf(m[4], m[5]), fmaxf(m[6], m[7]));  // [16,32)
        const float s1 = fmaxf(s3, fmaxf(m[4], r20));                  // [0,21)
        const float s2 = fmaxf(r11, fmaxf(m[3], s5));                  // [11,32)

        float* sd = segm[wib] + r * 7;    // stride 7: conflict-free
        sd[1] = s1; sd[2] = s2; sd[3] = s3; sd[4] = s4; sd[5] = s5;
        __syncwarp();                     // all lanes done reading ring + segm ready

        // Ring slot fully consumed -> refill it (commit group DEPTH+it).
        if (it + DEPTH < TPW) issue_tile(slot, it + DEPTH);

        // ---- 30 (segment, row-block) maxes ----
        if (lane < 30) {
            const int s   = 1 + lane / 6;
            const int blk = lane % 6;
            const int fam = (s >= 3);
            const int st  = c_start[fam][blk];
            const float* sp = segm[wib] + s;
            float bm = sp[st * 7];
#pragma unroll
            for (int qq = 1; qq < 5; qq++) bm = fmaxf(bm, sp[(st + qq) * 7]);
            if (c_sz6[fam][blk]) bm = fmaxf(bm, sp[(st + 5) * 7]);
            bmbuf[wib][lane] = bm;
        }
        __syncwarp();

        // ---- Region maxes into rsum (lanes 0/19 zero-pad) ----
        if (lane >= 1 && lane < 19) {
            const float* bp = bmbuf[wib];
            const int base = c_rbase[lane];
            float mm = fmaxf(fmaxf(bp[base], bp[base + 1]), bp[base + 2]);
            if (c_rcnt4[lane]) mm = fmaxf(mm, bp[base + 3]);
            rsum[wib][lane] = mm;
        } else if (lane == 19) {
            rsum[wib][19] = 0.0f;
        } else if (lane == 0) {
            rsum[wib][0] = 0.0f;
        }
        __syncwarp();

        // ---- Lane 0: full-image max + sum of 19 regions ----
        if (lane == 0) {
            const float4 b0 = *reinterpret_cast<const float4*>(&bmbuf[wib][0]);
            const float4 b1 = *reinterpret_cast<const float4*>(&bmbuf[wib][4]);
            const float4 b2 = *reinterpret_cast<const float4*>(&bmbuf[wib][8]);
            float full = fmaxf(fmaxf(fmaxf(b0.x, b0.y), fmaxf(b0.z, b0.w)),
                               fmaxf(fmaxf(b1.x, b1.y), fmaxf(b1.z, b1.w)));
            full = fmaxf(full, fmaxf(fmaxf(b2.x, b2.y), fmaxf(b2.z, b2.w)));

            const float4 q0 = *reinterpret_cast<const float4*>(&rsum[wib][0]);
            const float4 q1 = *reinterpret_cast<const float4*>(&rsum[wib][4]);
            const float4 q2 = *reinterpret_cast<const float4*>(&rsum[wib][8]);
            const float4 q3 = *reinterpret_cast<const float4*>(&rsum[wib][12]);
            const float4 q4 = *reinterpret_cast<const float4*>(&rsum[wib][16]);
            float acc = ((q0.x + q0.y) + (q0.z + q0.w))
                      + ((q1.x + q1.y) + (q1.z + q1.w))
                      + ((q2.x + q2.y) + (q2.z + q2.w))
                      + ((q3.x + q3.y) + (q3.z + q3.w))
                      + ((q4.x + q4.y) + (q4.z + q4.w))
                      + full;
            out[tbase + it] = acc;
        }
        __syncwarp();
    }
}

extern "C" void kernel_launch(void* const* d_in, const int* in_sizes, int n_in,
                              void* d_out, int out_size) {
    const float* x = (const float*)d_in[0];
    float* out = (float*)d_out;
    (void)in_sizes; (void)n_in; (void)out_size;
    // Opt-in dynamic smem above 48KB (idempotent host call; no allocation).
    cudaFuncSetAttribute(rmac_kernel,
                         cudaFuncAttributeMaxDynamicSharedMemorySize, DYN_SMEM);
    rmac_kernel<<<NTILES / (WPB * TPW), 32 * WPB, DYN_SMEM>>>(x, out);
}